// round 12
// baseline (speedup 1.0000x reference)
#include <cuda_runtime.h>
#include <cstddef>

// Problem constants (fixed by the dataset)
#define BS    32
#define NFEAT 64
#define NN    512      // N (graph nodes / m dim)
#define JJ    4
#define NOUT  128
#define CDIM  (JJ * NFEAT)        // 256 channels
#define ROWF4 512                 // one W n-row = 2048 floats = 512 float4
#define NCHUNK 16                 // chunk-blocks per batch in kernel 1
#define NPERCHUNK (NN / NCHUNK)   // 32 n-rows per block
#define EQ    8                   // epilogue m-groups per batch
#define MTL   (NN / EQ)           // 64 m per group

// Per-(b,chunk) partial sums of W over n. 32*16*2048 floats = 4 MB.
__device__ float g_Spart[BS * NCHUNK * 2048];
// Partial G per (b, m-group): 32*8*256 floats = 256 KB.
__device__ float g_Gpart[BS * EQ * CDIM];
// Per-batch completion counters; atomicInc wrap=EQ-1 self-resets every replay.
__device__ unsigned int g_cnt[BS];

// ---------------------------------------------------------------------------
// Kernel 1 (the 134 MB HBM stream) — proven shape; only addition is the PDL
// trigger so the epilogue's blocks launch into the ~80 spare block slots and
// stage X / warm fc_w while this kernel streams W.
// ---------------------------------------------------------------------------
__global__ __launch_bounds__(512) void reduce_w_kernel(const float4* __restrict__ W4) {
    cudaTriggerProgrammaticLaunchCompletion();

    const int chunk = blockIdx.x;
    const int b     = blockIdx.y;
    const int t     = threadIdx.x;          // 0..511

    const size_t row0 = ((size_t)b * NN + (size_t)chunk * NPERCHUNK) * ROWF4;
    const float4* __restrict__ base = W4 + row0;

    float4 acc = make_float4(0.f, 0.f, 0.f, 0.f);
#pragma unroll
    for (int i = 0; i < NPERCHUNK; ++i) {
        // streaming, evict-first: W is read exactly once and exceeds L2
        float4 v = __ldcs(&base[(size_t)i * ROWF4 + t]);
        acc.x += v.x; acc.y += v.y; acc.z += v.z; acc.w += v.w;
    }
    float4* out4 = reinterpret_cast<float4*>(g_Spart);
    out4[((size_t)b * NCHUNK + chunk) * ROWF4 + t] = acc;
}

// ---------------------------------------------------------------------------
// Kernel 2 (epilogue, PDL secondary). grid (BS, EQ) x 256 thr. Block (b,q)
// owns m-range [q*64, q*64+64):
//  pre-sync:  Xs[f][mloc] = X[b][f][q*64+mloc]  + fc_w L2 warm  (overlaps K1)
//  -- cudaGridDependencySynchronize() --
//  A: Ssh[j][mloc] = sum_c Spart[b][c][(q*64+mloc)*4+j]   (float4, 4-way split)
//  C: Gpart[b][q][c] = sum_mloc Ssh[j][mloc] * Xs[f][mloc] (shared only)
//  D (last block per batch): Gsh = sum_q Gpart; y = fc_w . Gsh + 512*fc_b
// ---------------------------------------------------------------------------
__global__ __launch_bounds__(256) void epilogue_kernel(
    const float* __restrict__ X,
    const float* __restrict__ fc_w,
    const float* __restrict__ fc_b,
    float* __restrict__ out)
{
    __shared__ float  Xs[NFEAT][MTL + 1]; // 16.6 KB, odd stride -> conflict-free
    __shared__ float4 red[256];           // 4 KB chunk-split partials
    __shared__ float  Ssh[JJ][MTL];       // 1 KB
    __shared__ float  Gsh[CDIM];          // 1 KB
    __shared__ int isLast;

    const int b = blockIdx.x;
    const int q = blockIdx.y;       // 0..7
    const int t = threadIdx.x;      // 0..255

    // ---- pre-sync: stage X tile [64][64] (float4, coalesced); overlaps K1 ----
    const float4* __restrict__ Xb4 =
        reinterpret_cast<const float4*>(X + (size_t)b * NFEAT * NN);
#pragma unroll
    for (int i = 0; i < 4; ++i) {
        const int idx = t + i * 256;             // 0..1023 f4 slots
        const int f   = idx >> 4;                // 16 f4 per f-row
        const int mq4 = idx & 15;
        const float4 v = Xb4[(size_t)f * (NN / 4) + q * (MTL / 4) + mq4];
        Xs[f][mq4 * 4 + 0] = v.x;
        Xs[f][mq4 * 4 + 1] = v.y;
        Xs[f][mq4 * 4 + 2] = v.z;
        Xs[f][mq4 * 4 + 3] = v.w;
    }
    // warm fc_w into L2 during K1 (q==0 blocks cover all 32*4KB = 128 KB)
    if (q == 0) {
        const float4* __restrict__ w4 = reinterpret_cast<const float4*>(fc_w);
        const float4 v = __ldg(&w4[b * 256 + t]);
        const float s = v.x + v.y + v.z + v.w;
        if (s == -1.2345678e33f) Gsh[0] = s;   // never taken; keeps the load live
    }

    // wait for kernel 1's Spart to be globally visible
    cudaGridDependencySynchronize();

    // ---- A: reduce chunk partials for f4-slots [q*64, q*64+64). Thread t
    // covers slot (t&63) for chunks [cgrp*4, cgrp*4+4), cgrp = t>>6. ----
    {
        const int sl4  = q * MTL + (t & 63);     // global f4 slot = m index
        const int cgrp = t >> 6;                 // 0..3
        const float4* __restrict__ part4 =
            reinterpret_cast<const float4*>(g_Spart) + (size_t)b * NCHUNK * 512 + sl4;
        float4 a = make_float4(0.f, 0.f, 0.f, 0.f);
#pragma unroll
        for (int k = 0; k < 4; ++k) {
            const float4 v = part4[(size_t)(cgrp * 4 + k) * 512];
            a.x += v.x; a.y += v.y; a.z += v.z; a.w += v.w;
        }
        red[t] = a;
    }
    __syncthreads();
    if (t < MTL) {
        float4 a = red[t];
        const float4 b1 = red[t + 64], b2 = red[t + 128], b3 = red[t + 192];
        a.x += b1.x + b2.x + b3.x;
        a.y += b1.y + b2.y + b3.y;
        a.z += b1.z + b2.z + b3.z;
        a.w += b1.w + b2.w + b3.w;
        Ssh[0][t] = a.x; Ssh[1][t] = a.y; Ssh[2][t] = a.z; Ssh[3][t] = a.w;
    }
    __syncthreads();

    // ---- C: partial G for all 256 channels, from shared only ----
    {
        const int j = t >> 6;      // uniform per warp -> Ssh broadcast
        const int f = t & 63;
        float g = 0.f;
#pragma unroll
        for (int mm = 0; mm < MTL; ++mm) g += Ssh[j][mm] * Xs[f][mm];
        g_Gpart[((size_t)b * EQ + q) * CDIM + t] = g;
    }

    // ---- gate: last block of batch b proceeds to D ----
    __threadfence();
    if (t == 0) {
        unsigned old = atomicInc(&g_cnt[b], EQ - 1);  // wraps to 0: self-resets
        isLast = (old == EQ - 1);
    }
    __syncthreads();
    if (!isLast) return;

    // ---- D: sum the 8 partials, then y ----
    {
        const float* __restrict__ gp = g_Gpart + (size_t)b * EQ * CDIM;
        float a = 0.f;
#pragma unroll
        for (int qq = 0; qq < EQ; ++qq) a += gp[(size_t)qq * CDIM + t];
        Gsh[t] = a;
    }
    __syncthreads();

    const int w    = t >> 5;        // warp 0..7
    const int lane = t & 31;
    const float4* __restrict__ Gsh4 = reinterpret_cast<const float4*>(Gsh);
#pragma unroll 2
    for (int oi = 0; oi < 16; ++oi) {
        const int o = w * 16 + oi;               // 0..127
        const float4* __restrict__ wrow4 =
            reinterpret_cast<const float4*>(fc_w + (size_t)o * CDIM);
        float a = 0.f;
#pragma unroll
        for (int i = 0; i < 2; ++i) {
            const int q4 = i * 32 + lane;        // 0..63 float4 slots
            const float4 wv = wrow4[q4];
            const float4 gv = Gsh4[q4];
            a += wv.x * gv.x + wv.y * gv.y + wv.z * gv.z + wv.w * gv.w;
        }
#pragma unroll
        for (int s = 16; s > 0; s >>= 1) a += __shfl_xor_sync(0xffffffffu, a, s);
        if (lane == 0) out[(size_t)b * NOUT + o] = a + (float)NN * fc_b[o];
    }
}

// ---------------------------------------------------------------------------
// Inputs (metadata order): X[32,64,512] f32, W[32,512,512,4] f32,
// fc_w[128,256] f32, fc_b[128] f32, N_batch (int), mask[32,512] f32 (unused).
// Output: y[32,128] f32.
// ---------------------------------------------------------------------------
extern "C" void kernel_launch(void* const* d_in, const int* in_sizes, int n_in,
                              void* d_out, int out_size)
{
    const float* X    = (const float*)d_in[0];
    const float* W    = (const float*)d_in[1];
    const float* fc_w = (const float*)d_in[2];
    const float* fc_b = (const float*)d_in[3];
    float*       out  = (float*)d_out;

    dim3 grid1(NCHUNK, BS);   // chunk fast, batch slow
    reduce_w_kernel<<<grid1, 512>>>(reinterpret_cast<const float4*>(W));

    // Epilogue as a PDL secondary: K1 triggers at its start, so these blocks
    // launch into spare slots, stage X / warm fc_w during the W stream, then
    // block in cudaGridDependencySynchronize until K1's stores are visible.
    cudaLaunchConfig_t cfg = {};
    cfg.gridDim  = dim3(BS, EQ);
    cfg.blockDim = dim3(256, 1, 1);
    cfg.dynamicSmemBytes = 0;
    cudaLaunchAttribute attrs[1];
    attrs[0].id = cudaLaunchAttributeProgrammaticStreamSerialization;
    attrs[0].val.programmaticStreamSerializationAllowed = 1;
    cfg.attrs = attrs;
    cfg.numAttrs = 1;
    cudaLaunchKernelEx(&cfg, epilogue_kernel, X, fc_w, fc_b, out);
}

// round 13
// speedup vs baseline: 1.0722x; 1.0722x over previous
#include <cuda_runtime.h>
#include <cstddef>

// Problem constants (fixed by the dataset)
#define BS    32
#define NFEAT 64
#define NN    512      // N (graph nodes / m dim)
#define JJ    4
#define NOUT  128
#define CDIM  (JJ * NFEAT)   // 256 channels
#define ROWF4 512            // one W n-row = 2048 floats = 512 float4
#define EQ    8              // epilogue m-groups per batch
#define MTL   (NN / EQ)      // 64 m per group

// Reduced, transposed S[b][j][m]. 32*4*512 floats = 256 KB (L2-resident).
__device__ float g_S[BS * JJ * NN];
// Partial G per (b, m-group): 32*8*256 floats = 256 KB.
__device__ float g_Gpart[BS * EQ * CDIM];
// Per-batch completion counters; atomicInc wrap=EQ-1 self-resets every replay.
__device__ unsigned int g_cnt[BS];

// ---------------------------------------------------------------------------
// Kernel 1 (the 134 MB HBM stream), column-split, writes S DIRECTLY.
// Block (s,b) owns float4 columns [s*16, s*16+16) of W[b] (i.e. m in that
// range). Thread t: col4 = t&15, ng = t>>4 (n-subgroup). Each thread sums 16
// rows (n = i*32+ng), fully unrolled -> MLP=16, same budget as the proven
// streamer. Warp load footprint = 16 consecutive float4 x 2 rows = 2x256B
// contiguous (full 128B lines). 1024 blocks x 512 thr = round-2 occupancy.
// Shared tree-reduce over the 32 n-subgroups, then transposed S write
// (components of the float4 ARE j=0..3).
// ---------------------------------------------------------------------------
__global__ __launch_bounds__(512) void reduce_w_kernel(const float4* __restrict__ W4) {
    __shared__ float4 red[512];   // 8 KB

    const int s = blockIdx.x;     // 0..31 column split
    const int b = blockIdx.y;
    const int t = threadIdx.x;    // 0..511
    const int col4 = t & 15;      // float4 column within slice = local m
    const int ng   = t >> 4;      // n-subgroup 0..31

    const float4* __restrict__ base =
        W4 + (size_t)b * NN * ROWF4 + s * 16 + col4;

    float4 acc = make_float4(0.f, 0.f, 0.f, 0.f);
#pragma unroll
    for (int i = 0; i < 16; ++i) {
        // streaming, evict-first: W is read exactly once and exceeds L2
        const float4 v = __ldcs(&base[(size_t)(i * 32 + ng) * ROWF4]);
        acc.x += v.x; acc.y += v.y; acc.z += v.z; acc.w += v.w;
    }
    red[t] = acc;                 // layout: red[ng*16 + col4]
    __syncthreads();

    // reduce over ng (strides are multiples of 16 -> col4 alignment preserved)
#pragma unroll
    for (int st = 256; st >= 16; st >>= 1) {
        if (t < st) {
            const float4 o = red[t + st];
            red[t].x += o.x; red[t].y += o.y; red[t].z += o.z; red[t].w += o.w;
        }
        __syncthreads();
    }

    if (t < 16) {
        const int m = s * 16 + t;
        const float4 r = red[t];
        g_S[((size_t)b * JJ + 0) * NN + m] = r.x;
        g_S[((size_t)b * JJ + 1) * NN + m] = r.y;
        g_S[((size_t)b * JJ + 2) * NN + m] = r.z;
        g_S[((size_t)b * JJ + 3) * NN + m] = r.w;
    }
}

// ---------------------------------------------------------------------------
// Kernel 2 (epilogue). grid (BS, EQ) x 256 thr. Block (b,q) owns m-range
// [q*64, q*64+64):
//  A: Ssh[j][mloc] = S[b][j][q*64+mloc]            (1 KB, L2-hot)
//     Xs[f][mloc]  = X[b][f][q*64+mloc]            (16 KB, float4 coalesced)
//  C: Gpart[b][q][c] = sum_mloc Ssh[j][mloc]*Xs[f][mloc]   (shared only)
//  D (last block per batch, wrap-gated): Gsh = sum_q Gpart;
//     y[b][o] = fc_w[o,:] . Gsh + 512*fc_b[o]
// ---------------------------------------------------------------------------
__global__ __launch_bounds__(256) void epilogue_kernel(
    const float* __restrict__ X,
    const float* __restrict__ fc_w,
    const float* __restrict__ fc_b,
    float* __restrict__ out)
{
    __shared__ float Xs[NFEAT][MTL + 1]; // 16.25 KB, odd stride -> conflict-free
    __shared__ float Ssh[JJ][MTL];       // 1 KB
    __shared__ float Gsh[CDIM];          // 1 KB
    __shared__ int isLast;

    const int b = blockIdx.x;
    const int q = blockIdx.y;       // 0..7
    const int t = threadIdx.x;      // 0..255

    // ---- A: S slice + X tile (issued together; independent loads) ----
    {
        const int j    = t >> 6;     // 0..3
        const int mloc = t & 63;
        Ssh[j][mloc] = g_S[((size_t)b * JJ + j) * NN + q * MTL + mloc];
    }
    const float4* __restrict__ Xb4 =
        reinterpret_cast<const float4*>(X + (size_t)b * NFEAT * NN);
#pragma unroll
    for (int i = 0; i < 4; ++i) {
        const int idx = t + i * 256;             // 0..1023 f4 slots
        const int f   = idx >> 4;                // 16 f4 per f-row
        const int mq4 = idx & 15;
        const float4 v = Xb4[(size_t)f * (NN / 4) + q * (MTL / 4) + mq4];
        Xs[f][mq4 * 4 + 0] = v.x;
        Xs[f][mq4 * 4 + 1] = v.y;
        Xs[f][mq4 * 4 + 2] = v.z;
        Xs[f][mq4 * 4 + 3] = v.w;
    }
    __syncthreads();

    // ---- C: partial G for all 256 channels, from shared only ----
    {
        const int j = t >> 6;      // uniform per warp -> Ssh broadcast
        const int f = t & 63;
        float g = 0.f;
#pragma unroll
        for (int mm = 0; mm < MTL; ++mm) g += Ssh[j][mm] * Xs[f][mm];
        g_Gpart[((size_t)b * EQ + q) * CDIM + t] = g;
    }

    // ---- gate: last block of batch b proceeds to D ----
    __threadfence();
    if (t == 0) {
        unsigned old = atomicInc(&g_cnt[b], EQ - 1);  // wraps to 0: self-resets
        isLast = (old == EQ - 1);
    }
    __syncthreads();
    if (!isLast) return;

    // ---- D: sum the 8 partials (L2-hot), then y ----
    {
        const float* __restrict__ gp = g_Gpart + (size_t)b * EQ * CDIM;
        float a = 0.f;
#pragma unroll
        for (int qq = 0; qq < EQ; ++qq) a += gp[(size_t)qq * CDIM + t];
        Gsh[t] = a;
    }
    __syncthreads();

    const int w    = t >> 5;        // warp 0..7
    const int lane = t & 31;
    const float4* __restrict__ Gsh4 = reinterpret_cast<const float4*>(Gsh);
#pragma unroll 2
    for (int oi = 0; oi < 16; ++oi) {
        const int o = w * 16 + oi;               // 0..127
        const float4* __restrict__ wrow4 =
            reinterpret_cast<const float4*>(fc_w + (size_t)o * CDIM);
        float a = 0.f;
#pragma unroll
        for (int i = 0; i < 2; ++i) {
            const int q4 = i * 32 + lane;        // 0..63 float4 slots
            const float4 wv = wrow4[q4];
            const float4 gv = Gsh4[q4];
            a += wv.x * gv.x + wv.y * gv.y + wv.z * gv.z + wv.w * gv.w;
        }
#pragma unroll
        for (int s = 16; s > 0; s >>= 1) a += __shfl_xor_sync(0xffffffffu, a, s);
        if (lane == 0) out[(size_t)b * NOUT + o] = a + (float)NN * fc_b[o];
    }
}

// ---------------------------------------------------------------------------
// Inputs (metadata order): X[32,64,512] f32, W[32,512,512,4] f32,
// fc_w[128,256] f32, fc_b[128] f32, N_batch (int), mask[32,512] f32 (unused).
// Output: y[32,128] f32.
// ---------------------------------------------------------------------------
extern "C" void kernel_launch(void* const* d_in, const int* in_sizes, int n_in,
                              void* d_out, int out_size)
{
    const float* X    = (const float*)d_in[0];
    const float* W    = (const float*)d_in[1];
    const float* fc_w = (const float*)d_in[2];
    const float* fc_b = (const float*)d_in[3];
    float*       out  = (float*)d_out;

    dim3 grid1(32, BS);   // (column-split, batch)
    reduce_w_kernel<<<grid1, 512>>>(reinterpret_cast<const float4*>(W));
    dim3 grid2(BS, EQ);
    epilogue_kernel<<<grid2, 256>>>(X, fc_w, fc_b, out);
}